// round 12
// baseline (speedup 1.0000x reference)
#include <cuda_runtime.h>
#include <math_constants.h>

#define B_    64
#define C_    256
#define HW_   4096          // floats per plane = 1024 float4
#define NPLANE (B_*C_)      // 16384
#define NCL   8

__device__ float g_sum[NPLANE];
__device__ float g_min[NPLANE];
__device__ float g_max[NPLANE];
__device__ float g_scale[NPLANE];
__device__ float g_smin[B_];
__device__ float g_smax[B_];
__device__ float g_ss[B_];
__device__ float g_zz[B_];
__device__ float g_inv[B_];
__device__ unsigned g_k2cnt;   // self-resetting counter for k2's finisher

// ---------------- kernel 1: per-plane sum/min/max, warp-per-plane (proven) --
__global__ __launch_bounds__(256) void k1_reduce(const float* __restrict__ x) {
    const int warp  = threadIdx.x >> 5;
    const int lane  = threadIdx.x & 31;
    const int plane = blockIdx.x * 8 + warp;

    const float4* xp = reinterpret_cast<const float4*>(x + (size_t)plane * HW_);

    float s0 = 0.f, s1 = 0.f;
    float mn0 = CUDART_INF_F, mn1 = CUDART_INF_F;
    float mx0 = -CUDART_INF_F, mx1 = -CUDART_INF_F;
#pragma unroll 4
    for (int i = 0; i < 32; i += 2) {
        float4 a = xp[lane + 32 * i];
        float4 b = xp[lane + 32 * (i + 1)];
        s0 += (a.x + a.y) + (a.z + a.w);
        mn0 = fminf(mn0, fminf(fminf(a.x, a.y), fminf(a.z, a.w)));
        mx0 = fmaxf(mx0, fmaxf(fmaxf(a.x, a.y), fmaxf(a.z, a.w)));
        s1 += (b.x + b.y) + (b.z + b.w);
        mn1 = fminf(mn1, fminf(fminf(b.x, b.y), fminf(b.z, b.w)));
        mx1 = fmaxf(mx1, fmaxf(fmaxf(b.x, b.y), fmaxf(b.z, b.w)));
    }
    float s  = s0 + s1;
    float mn = fminf(mn0, mn1);
    float mx = fmaxf(mx0, mx1);
#pragma unroll
    for (int o = 16; o; o >>= 1) {
        s  += __shfl_xor_sync(0xffffffffu, s, o);
        mn  = fminf(mn, __shfl_xor_sync(0xffffffffu, mn, o));
        mx  = fmaxf(mx, __shfl_xor_sync(0xffffffffu, mx, o));
    }
    if (lane == 0) {
        g_sum[plane] = s;
        g_min[plane] = mn;
        g_max[plane] = mx;
    }
}

// ---------------- kernel 2: SE MLP + per-sample min/max + inline k3 (proven) -
__global__ __launch_bounds__(256) void k2_se(const float* __restrict__ w1,
                                             const float* __restrict__ b1,
                                             const float* __restrict__ w2,
                                             const float* __restrict__ b2,
                                             const float* __restrict__ act_range,
                                             const int*   __restrict__ cluster) {
    const int b = blockIdx.x;
    const int t = threadIdx.x;
    const int lane = t & 31, warp = t >> 5;
    __shared__ float pooled[C_];
    __shared__ float hbuf[64];

    pooled[t] = g_sum[b * C_ + t] * (1.0f / 4096.0f);
    __syncthreads();

#pragma unroll
    for (int k = 0; k < 8; ++k) {                 // 8 warps x 8 outputs, coalesced
        const int o = warp * 8 + k;
        const float* row = w1 + o * C_;
        float acc = 0.f;
#pragma unroll
        for (int j = 0; j < 8; ++j)
            acc = fmaf(row[lane + 32 * j], pooled[lane + 32 * j], acc);
#pragma unroll
        for (int sh = 16; sh; sh >>= 1)
            acc += __shfl_xor_sync(0xffffffffu, acc, sh);
        if (lane == 0) hbuf[o] = fmaxf(acc + b1[o], 0.0f);
    }
    __syncthreads();

    float v = b2[t];
    const float4* w2r = reinterpret_cast<const float4*>(w2 + t * 64);
#pragma unroll
    for (int j = 0; j < 16; ++j) {
        float4 wv = w2r[j];
        v = fmaf(hbuf[4 * j + 0], wv.x, v);
        v = fmaf(hbuf[4 * j + 1], wv.y, v);
        v = fmaf(hbuf[4 * j + 2], wv.z, v);
        v = fmaf(hbuf[4 * j + 3], wv.w, v);
    }
    float sc = fminf(fmaxf(v * (1.0f / 6.0f) + 0.5f, 0.0f), 1.0f);
    g_scale[b * C_ + t] = sc;

    float pmn = sc * g_min[b * C_ + t];           // scale >= 0
    float pmx = sc * g_max[b * C_ + t];
#pragma unroll
    for (int o = 16; o; o >>= 1) {
        pmn = fminf(pmn, __shfl_xor_sync(0xffffffffu, pmn, o));
        pmx = fmaxf(pmx, __shfl_xor_sync(0xffffffffu, pmx, o));
    }
    __shared__ float sh_mn[8], sh_mx[8];
    if (lane == 0) { sh_mn[warp] = pmn; sh_mx[warp] = pmx; }
    __syncthreads();
    if (t == 0) {
        float tmn = CUDART_INF_F, tmx = -CUDART_INF_F;
#pragma unroll
        for (int w = 0; w < 8; ++w) {
            tmn = fminf(tmn, sh_mn[w]);
            tmx = fmaxf(tmx, sh_mx[w]);
        }
        g_smin[b] = tmn;
        g_smax[b] = tmx;
    }
    __syncthreads();

    // ---- last-finishing block runs the (tiny) cluster-range stage ----
    __shared__ int sh_last;
    if (t == 0) {
        __threadfence();                           // release smin/smax/scale
        unsigned old = atomicAdd(&g_k2cnt, 1u);
        sh_last = (old == B_ - 1u);
        if (sh_last) g_k2cnt = 0u;                 // reset for graph replay
    }
    __syncthreads();
    if (!sh_last) return;
    __threadfence();                               // acquire peers' smin/smax

    __shared__ float cs_s[NCL], cs_z[NCL];
    if (t < NCL) {
        float cmin = CUDART_INF_F, cmax = -CUDART_INF_F;
        for (int bb = 0; bb < B_; ++bb) {
            if (cluster[bb] == t) {
                cmin = fminf(cmin, g_smin[bb]);
                cmax = fmaxf(cmax, g_smax[bb]);
            }
        }
        const float SMOOTH = 0.995f, ONE_M = 0.005f;
        float nmin = act_range[2 * t]     * SMOOTH + cmin * ONE_M;
        float nmax = act_range[2 * t + 1] * SMOOTH + cmax * ONE_M;
        float s = (nmax - nmin) * (1.0f / 255.0f);
        cs_s[t] = s;
        cs_z[t] = -rintf(nmin / s);
    }
    __syncthreads();
    if (t < B_) {
        int k = cluster[t];
        g_ss[t]  = cs_s[k];
        g_zz[t]  = cs_z[k];
        g_inv[t] = 1.0f / cs_s[k];
    }
}

// ---------------- kernel 4: fake-quant (R9 known-good: 73.7us @ 82.5% DRAM) -
__global__ __launch_bounds__(256) void k4_quant(const float* __restrict__ x,
                                                float* __restrict__ out) {
    const int plane = blockIdx.x;
    const int b = plane >> 8;
    const float sc  = g_scale[plane];
    const float ssv = g_ss[b];
    const float zzv = g_zz[b];
    const float inv = g_inv[b];

    const float4* xp = reinterpret_cast<const float4*>(x   + (size_t)plane * HW_);
    float4*       op = reinterpret_cast<float4*>      (out + (size_t)plane * HW_);

#pragma unroll
    for (int i = 0; i < 4; ++i) {
        float4 v = xp[threadIdx.x + 256 * i];
        float4 r;
        {
            float o = sc * v.x;
            float q = fminf(fmaxf(rintf(fmaf(o, inv, zzv)), 0.0f), 255.0f);
            r.x = (q - zzv) * ssv;
        }
        {
            float o = sc * v.y;
            float q = fminf(fmaxf(rintf(fmaf(o, inv, zzv)), 0.0f), 255.0f);
            r.y = (q - zzv) * ssv;
        }
        {
            float o = sc * v.z;
            float q = fminf(fmaxf(rintf(fmaf(o, inv, zzv)), 0.0f), 255.0f);
            r.z = (q - zzv) * ssv;
        }
        {
            float o = sc * v.w;
            float q = fminf(fmaxf(rintf(fmaf(o, inv, zzv)), 0.0f), 255.0f);
            r.w = (q - zzv) * ssv;
        }
        op[threadIdx.x + 256 * i] = r;
    }
}

// ---------------- launch ----------------------------------------------------
extern "C" void kernel_launch(void* const* d_in, const int* in_sizes, int n_in,
                              void* d_out, int out_size) {
    const float* x          = (const float*)d_in[0];
    const float* w1         = (const float*)d_in[1];
    const float* b1         = (const float*)d_in[2];
    const float* w2         = (const float*)d_in[3];
    const float* b2         = (const float*)d_in[4];
    const float* act_range  = (const float*)d_in[5];
    const int*   cluster    = (const int*)d_in[6];
    float* out = (float*)d_out;

    k1_reduce<<<NPLANE / 8, 256>>>(x);
    k2_se<<<B_, 256>>>(w1, b1, w2, b2, act_range, cluster);
    k4_quant<<<NPLANE, 256>>>(x, out);
}

// round 13
// speedup vs baseline: 1.0610x; 1.0610x over previous
#include <cuda_runtime.h>
#include <math_constants.h>

#define B_    64
#define C_    256
#define HW_   4096          // floats per plane = 1024 float4
#define NPLANE (B_*C_)      // 16384
#define NCL   8

__device__ float g_sum[NPLANE];
__device__ float g_min[NPLANE];
__device__ float g_max[NPLANE];
__device__ float g_scale[NPLANE];
__device__ float g_smin[B_];
__device__ float g_smax[B_];
__device__ float g_ss[B_];
__device__ float g_zz[B_];
__device__ float g_inv[B_];

// ---------------- kernel 1: per-plane sum/min/max, warp-per-plane (proven) --
__global__ __launch_bounds__(256) void k1_reduce(const float* __restrict__ x) {
    const int warp  = threadIdx.x >> 5;
    const int lane  = threadIdx.x & 31;
    const int plane = blockIdx.x * 8 + warp;

    const float4* xp = reinterpret_cast<const float4*>(x + (size_t)plane * HW_);

    float s0 = 0.f, s1 = 0.f;
    float mn0 = CUDART_INF_F, mn1 = CUDART_INF_F;
    float mx0 = -CUDART_INF_F, mx1 = -CUDART_INF_F;
#pragma unroll 4
    for (int i = 0; i < 32; i += 2) {
        float4 a = xp[lane + 32 * i];
        float4 b = xp[lane + 32 * (i + 1)];
        s0 += (a.x + a.y) + (a.z + a.w);
        mn0 = fminf(mn0, fminf(fminf(a.x, a.y), fminf(a.z, a.w)));
        mx0 = fmaxf(mx0, fmaxf(fmaxf(a.x, a.y), fmaxf(a.z, a.w)));
        s1 += (b.x + b.y) + (b.z + b.w);
        mn1 = fminf(mn1, fminf(fminf(b.x, b.y), fminf(b.z, b.w)));
        mx1 = fmaxf(mx1, fmaxf(fmaxf(b.x, b.y), fmaxf(b.z, b.w)));
    }
    float s  = s0 + s1;
    float mn = fminf(mn0, mn1);
    float mx = fmaxf(mx0, mx1);
#pragma unroll
    for (int o = 16; o; o >>= 1) {
        s  += __shfl_xor_sync(0xffffffffu, s, o);
        mn  = fminf(mn, __shfl_xor_sync(0xffffffffu, mn, o));
        mx  = fmaxf(mx, __shfl_xor_sync(0xffffffffu, mx, o));
    }
    if (lane == 0) {
        g_sum[plane] = s;
        g_min[plane] = mn;
        g_max[plane] = mx;
    }
}

// ---------------- kernel 2: SE MLP + per-sample min/max (R9 proven) ---------
__global__ __launch_bounds__(256) void k2_se(const float* __restrict__ w1,
                                             const float* __restrict__ b1,
                                             const float* __restrict__ w2,
                                             const float* __restrict__ b2) {
    const int b = blockIdx.x;
    const int t = threadIdx.x;
    const int lane = t & 31, warp = t >> 5;
    __shared__ float pooled[C_];
    __shared__ float hbuf[64];

    pooled[t] = g_sum[b * C_ + t] * (1.0f / 4096.0f);
    __syncthreads();

#pragma unroll
    for (int k = 0; k < 8; ++k) {                 // 8 warps x 8 outputs, coalesced
        const int o = warp * 8 + k;
        const float* row = w1 + o * C_;
        float acc = 0.f;
#pragma unroll
        for (int j = 0; j < 8; ++j)
            acc = fmaf(row[lane + 32 * j], pooled[lane + 32 * j], acc);
#pragma unroll
        for (int sh = 16; sh; sh >>= 1)
            acc += __shfl_xor_sync(0xffffffffu, acc, sh);
        if (lane == 0) hbuf[o] = fmaxf(acc + b1[o], 0.0f);
    }
    __syncthreads();

    float v = b2[t];
    const float4* w2r = reinterpret_cast<const float4*>(w2 + t * 64);
#pragma unroll
    for (int j = 0; j < 16; ++j) {
        float4 wv = w2r[j];
        v = fmaf(hbuf[4 * j + 0], wv.x, v);
        v = fmaf(hbuf[4 * j + 1], wv.y, v);
        v = fmaf(hbuf[4 * j + 2], wv.z, v);
        v = fmaf(hbuf[4 * j + 3], wv.w, v);
    }
    float sc = fminf(fmaxf(v * (1.0f / 6.0f) + 0.5f, 0.0f), 1.0f);
    g_scale[b * C_ + t] = sc;

    float pmn = sc * g_min[b * C_ + t];           // scale >= 0
    float pmx = sc * g_max[b * C_ + t];
#pragma unroll
    for (int o = 16; o; o >>= 1) {
        pmn = fminf(pmn, __shfl_xor_sync(0xffffffffu, pmn, o));
        pmx = fmaxf(pmx, __shfl_xor_sync(0xffffffffu, pmx, o));
    }
    __shared__ float sh_mn[8], sh_mx[8];
    if (lane == 0) { sh_mn[warp] = pmn; sh_mx[warp] = pmx; }
    __syncthreads();
    if (t == 0) {
        float tmn = CUDART_INF_F, tmx = -CUDART_INF_F;
#pragma unroll
        for (int w = 0; w < 8; ++w) {
            tmn = fminf(tmn, sh_mn[w]);
            tmx = fmaxf(tmx, sh_mx[w]);
        }
        g_smin[b] = tmn;
        g_smax[b] = tmx;
    }
}

// ---------------- kernel 3: cluster EMA ranges + per-sample (s,z) -----------
__global__ __launch_bounds__(64) void k3_ranges(const float* __restrict__ act_range,
                                                const int* __restrict__ cluster) {
    __shared__ float s_s[NCL], s_z[NCL];
    const int t = threadIdx.x;
    if (t < NCL) {
        float cmin = CUDART_INF_F, cmax = -CUDART_INF_F;
        for (int b = 0; b < B_; ++b) {
            if (cluster[b] == t) {
                cmin = fminf(cmin, g_smin[b]);
                cmax = fmaxf(cmax, g_smax[b]);
            }
        }
        const float SMOOTH = 0.995f, ONE_M = 0.005f;
        float nmin = act_range[2 * t]     * SMOOTH + cmin * ONE_M;
        float nmax = act_range[2 * t + 1] * SMOOTH + cmax * ONE_M;
        float s = (nmax - nmin) * (1.0f / 255.0f);
        s_s[t] = s;
        s_z[t] = -rintf(nmin / s);
    }
    __syncthreads();
    if (t < B_) {
        int k = cluster[t];
        g_ss[t]  = s_s[k];
        g_zz[t]  = s_z[k];
        g_inv[t] = 1.0f / s_s[k];
    }
}

// ---------------- kernel 4: fake-quant, REVERSED plane order ----------------
// Only delta vs the proven R9 k4: plane = 16383 - blockIdx.x. k1 read planes
// ascending, so the top ~126MB of x is L2-resident; k4's first waves read it.
// No cache hints — default policy retains lines normally.
__global__ __launch_bounds__(256) void k4_quant(const float* __restrict__ x,
                                                float* __restrict__ out) {
    const int plane = (NPLANE - 1) - blockIdx.x;
    const int b = plane >> 8;
    const float sc  = g_scale[plane];
    const float ssv = g_ss[b];
    const float zzv = g_zz[b];
    const float inv = g_inv[b];

    const float4* xp = reinterpret_cast<const float4*>(x   + (size_t)plane * HW_);
    float4*       op = reinterpret_cast<float4*>      (out + (size_t)plane * HW_);

#pragma unroll
    for (int i = 0; i < 4; ++i) {
        float4 v = xp[threadIdx.x + 256 * i];
        float4 r;
        {
            float o = sc * v.x;
            float q = fminf(fmaxf(rintf(fmaf(o, inv, zzv)), 0.0f), 255.0f);
            r.x = (q - zzv) * ssv;
        }
        {
            float o = sc * v.y;
            float q = fminf(fmaxf(rintf(fmaf(o, inv, zzv)), 0.0f), 255.0f);
            r.y = (q - zzv) * ssv;
        }
        {
            float o = sc * v.z;
            float q = fminf(fmaxf(rintf(fmaf(o, inv, zzv)), 0.0f), 255.0f);
            r.z = (q - zzv) * ssv;
        }
        {
            float o = sc * v.w;
            float q = fminf(fmaxf(rintf(fmaf(o, inv, zzv)), 0.0f), 255.0f);
            r.w = (q - zzv) * ssv;
        }
        op[threadIdx.x + 256 * i] = r;
    }
}

// ---------------- launch ----------------------------------------------------
extern "C" void kernel_launch(void* const* d_in, const int* in_sizes, int n_in,
                              void* d_out, int out_size) {
    const float* x          = (const float*)d_in[0];
    const float* w1         = (const float*)d_in[1];
    const float* b1         = (const float*)d_in[2];
    const float* w2         = (const float*)d_in[3];
    const float* b2         = (const float*)d_in[4];
    const float* act_range  = (const float*)d_in[5];
    const int*   cluster    = (const int*)d_in[6];
    float* out = (float*)d_out;

    k1_reduce<<<NPLANE / 8, 256>>>(x);
    k2_se<<<B_, 256>>>(w1, b1, w2, b2);
    k3_ranges<<<1, 64>>>(act_range, cluster);
    k4_quant<<<NPLANE, 256>>>(x, out);
}

// round 15
// speedup vs baseline: 1.0661x; 1.0048x over previous
#include <cuda_runtime.h>
#include <math_constants.h>

#define B_    64
#define C_    256
#define HW_   4096          // floats per plane = 1024 float4
#define NPLANE (B_*C_)      // 16384
#define NCL   8

__device__ float g_sum[NPLANE];
__device__ float g_min[NPLANE];
__device__ float g_max[NPLANE];
__device__ float g_scale[NPLANE];
__device__ float g_smin[B_];
__device__ float g_smax[B_];
__device__ float g_ss[B_];
__device__ float g_zz[B_];
__device__ float g_inv[B_];

// ---------------- kernel 1: per-plane sum/min/max, warp-per-plane (proven) --
__global__ __launch_bounds__(256) void k1_reduce(const float* __restrict__ x) {
    const int warp  = threadIdx.x >> 5;
    const int lane  = threadIdx.x & 31;
    const int plane = blockIdx.x * 8 + warp;

    const float4* xp = reinterpret_cast<const float4*>(x + (size_t)plane * HW_);

    float s0 = 0.f, s1 = 0.f;
    float mn0 = CUDART_INF_F, mn1 = CUDART_INF_F;
    float mx0 = -CUDART_INF_F, mx1 = -CUDART_INF_F;
#pragma unroll 4
    for (int i = 0; i < 32; i += 2) {
        float4 a = xp[lane + 32 * i];
        float4 b = xp[lane + 32 * (i + 1)];
        s0 += (a.x + a.y) + (a.z + a.w);
        mn0 = fminf(mn0, fminf(fminf(a.x, a.y), fminf(a.z, a.w)));
        mx0 = fmaxf(mx0, fmaxf(fmaxf(a.x, a.y), fmaxf(a.z, a.w)));
        s1 += (b.x + b.y) + (b.z + b.w);
        mn1 = fminf(mn1, fminf(fminf(b.x, b.y), fminf(b.z, b.w)));
        mx1 = fmaxf(mx1, fmaxf(fmaxf(b.x, b.y), fmaxf(b.z, b.w)));
    }
    float s  = s0 + s1;
    float mn = fminf(mn0, mn1);
    float mx = fmaxf(mx0, mx1);
#pragma unroll
    for (int o = 16; o; o >>= 1) {
        s  += __shfl_xor_sync(0xffffffffu, s, o);
        mn  = fminf(mn, __shfl_xor_sync(0xffffffffu, mn, o));
        mx  = fmaxf(mx, __shfl_xor_sync(0xffffffffu, mx, o));
    }
    if (lane == 0) {
        g_sum[plane] = s;
        g_min[plane] = mn;
        g_max[plane] = mx;
    }
}

// ---------------- kernel 2: SE MLP + per-sample min/max (proven) ------------
__global__ __launch_bounds__(256) void k2_se(const float* __restrict__ w1,
                                             const float* __restrict__ b1,
                                             const float* __restrict__ w2,
                                             const float* __restrict__ b2) {
    const int b = blockIdx.x;
    const int t = threadIdx.x;
    const int lane = t & 31, warp = t >> 5;
    __shared__ float pooled[C_];
    __shared__ float hbuf[64];

    pooled[t] = g_sum[b * C_ + t] * (1.0f / 4096.0f);
    __syncthreads();

#pragma unroll
    for (int k = 0; k < 8; ++k) {                 // 8 warps x 8 outputs, coalesced
        const int o = warp * 8 + k;
        const float* row = w1 + o * C_;
        float acc = 0.f;
#pragma unroll
        for (int j = 0; j < 8; ++j)
            acc = fmaf(row[lane + 32 * j], pooled[lane + 32 * j], acc);
#pragma unroll
        for (int sh = 16; sh; sh >>= 1)
            acc += __shfl_xor_sync(0xffffffffu, acc, sh);
        if (lane == 0) hbuf[o] = fmaxf(acc + b1[o], 0.0f);
    }
    __syncthreads();

    float v = b2[t];
    const float4* w2r = reinterpret_cast<const float4*>(w2 + t * 64);
#pragma unroll
    for (int j = 0; j < 16; ++j) {
        float4 wv = w2r[j];
        v = fmaf(hbuf[4 * j + 0], wv.x, v);
        v = fmaf(hbuf[4 * j + 1], wv.y, v);
        v = fmaf(hbuf[4 * j + 2], wv.z, v);
        v = fmaf(hbuf[4 * j + 3], wv.w, v);
    }
    float sc = fminf(fmaxf(v * (1.0f / 6.0f) + 0.5f, 0.0f), 1.0f);
    g_scale[b * C_ + t] = sc;

    float pmn = sc * g_min[b * C_ + t];           // scale >= 0
    float pmx = sc * g_max[b * C_ + t];
#pragma unroll
    for (int o = 16; o; o >>= 1) {
        pmn = fminf(pmn, __shfl_xor_sync(0xffffffffu, pmn, o));
        pmx = fmaxf(pmx, __shfl_xor_sync(0xffffffffu, pmx, o));
    }
    __shared__ float sh_mn[8], sh_mx[8];
    if (lane == 0) { sh_mn[warp] = pmn; sh_mx[warp] = pmx; }
    __syncthreads();
    if (t == 0) {
        float tmn = CUDART_INF_F, tmx = -CUDART_INF_F;
#pragma unroll
        for (int w = 0; w < 8; ++w) {
            tmn = fminf(tmn, sh_mn[w]);
            tmx = fmaxf(tmx, sh_mx[w]);
        }
        g_smin[b] = tmn;
        g_smax[b] = tmx;
    }
}

// ---------------- kernel 3: cluster EMA ranges + per-sample (s,z) -----------
__global__ __launch_bounds__(64) void k3_ranges(const float* __restrict__ act_range,
                                                const int* __restrict__ cluster) {
    __shared__ float s_s[NCL], s_z[NCL];
    const int t = threadIdx.x;
    if (t < NCL) {
        float cmin = CUDART_INF_F, cmax = -CUDART_INF_F;
        for (int b = 0; b < B_; ++b) {
            if (cluster[b] == t) {
                cmin = fminf(cmin, g_smin[b]);
                cmax = fmaxf(cmax, g_smax[b]);
            }
        }
        const float SMOOTH = 0.995f, ONE_M = 0.005f;
        float nmin = act_range[2 * t]     * SMOOTH + cmin * ONE_M;
        float nmax = act_range[2 * t + 1] * SMOOTH + cmax * ONE_M;
        float s = (nmax - nmin) * (1.0f / 255.0f);
        s_s[t] = s;
        s_z[t] = -rintf(nmin / s);
    }
    __syncthreads();
    if (t < B_) {
        int k = cluster[t];
        g_ss[t]  = s_s[k];
        g_zz[t]  = s_z[k];
        g_inv[t] = 1.0f / s_s[k];
    }
}

// ---------------- kernel 4: fake-quant, reversed + WRITE-THROUGH stores -----
// R13 (proven 133.9us total) + one change: __stwt on out. Out lines are
// written once and never read — write-through keeps them out of L2, so the
// x lines left by k1 (and streamed during k4) survive longer -> more L2 hits.
__global__ __launch_bounds__(256) void k4_quant(const float* __restrict__ x,
                                                float* __restrict__ out) {
    const int plane = (NPLANE - 1) - blockIdx.x;
    const int b = plane >> 8;
    const float sc  = g_scale[plane];
    const float ssv = g_ss[b];
    const float zzv = g_zz[b];
    const float inv = g_inv[b];

    const float4* xp = reinterpret_cast<const float4*>(x   + (size_t)plane * HW_);
    float4*       op = reinterpret_cast<float4*>      (out + (size_t)plane * HW_);

#pragma unroll
    for (int i = 0; i < 4; ++i) {
        float4 v = xp[threadIdx.x + 256 * i];
        float4 r;
        {
            float o = sc * v.x;
            float q = fminf(fmaxf(rintf(fmaf(o, inv, zzv)), 0.0f), 255.0f);
            r.x = (q - zzv) * ssv;
        }
        {
            float o = sc * v.y;
            float q = fminf(fmaxf(rintf(fmaf(o, inv, zzv)), 0.0f), 255.0f);
            r.y = (q - zzv) * ssv;
        }
        {
            float o = sc * v.z;
            float q = fminf(fmaxf(rintf(fmaf(o, inv, zzv)), 0.0f), 255.0f);
            r.z = (q - zzv) * ssv;
        }
        {
            float o = sc * v.w;
            float q = fminf(fmaxf(rintf(fmaf(o, inv, zzv)), 0.0f), 255.0f);
            r.w = (q - zzv) * ssv;
        }
        __stwt(&op[threadIdx.x + 256 * i], r);
    }
}

// ---------------- launch ----------------------------------------------------
extern "C" void kernel_launch(void* const* d_in, const int* in_sizes, int n_in,
                              void* d_out, int out_size) {
    const float* x          = (const float*)d_in[0];
    const float* w1         = (const float*)d_in[1];
    const float* b1         = (const float*)d_in[2];
    const float* w2         = (const float*)d_in[3];
    const float* b2         = (const float*)d_in[4];
    const float* act_range  = (const float*)d_in[5];
    const int*   cluster    = (const int*)d_in[6];
    float* out = (float*)d_out;

    k1_reduce<<<NPLANE / 8, 256>>>(x);
    k2_se<<<B_, 256>>>(w1, b1, w2, b2);
    k3_ranges<<<1, 64>>>(act_range, cluster);
    k4_quant<<<NPLANE, 256>>>(x, out);
}

// round 16
// speedup vs baseline: 1.0848x; 1.0176x over previous
#include <cuda_runtime.h>
#include <math_constants.h>

#define B_    64
#define C_    256
#define HW_   4096          // floats per plane = 1024 float4
#define NPLANE (B_*C_)      // 16384
#define NCL   8

__device__ float g_sum[NPLANE];
__device__ float g_min[NPLANE];
__device__ float g_max[NPLANE];
__device__ float g_scale[NPLANE];
__device__ float g_smin[B_];
__device__ float g_smax[B_];

// ---------------- kernel 1: per-plane sum/min/max, warp-per-plane (proven) --
__global__ __launch_bounds__(256) void k1_reduce(const float* __restrict__ x) {
    const int warp  = threadIdx.x >> 5;
    const int lane  = threadIdx.x & 31;
    const int plane = blockIdx.x * 8 + warp;

    const float4* xp = reinterpret_cast<const float4*>(x + (size_t)plane * HW_);

    float s0 = 0.f, s1 = 0.f;
    float mn0 = CUDART_INF_F, mn1 = CUDART_INF_F;
    float mx0 = -CUDART_INF_F, mx1 = -CUDART_INF_F;
#pragma unroll 4
    for (int i = 0; i < 32; i += 2) {
        float4 a = xp[lane + 32 * i];
        float4 b = xp[lane + 32 * (i + 1)];
        s0 += (a.x + a.y) + (a.z + a.w);
        mn0 = fminf(mn0, fminf(fminf(a.x, a.y), fminf(a.z, a.w)));
        mx0 = fmaxf(mx0, fmaxf(fmaxf(a.x, a.y), fmaxf(a.z, a.w)));
        s1 += (b.x + b.y) + (b.z + b.w);
        mn1 = fminf(mn1, fminf(fminf(b.x, b.y), fminf(b.z, b.w)));
        mx1 = fmaxf(mx1, fmaxf(fmaxf(b.x, b.y), fmaxf(b.z, b.w)));
    }
    float s  = s0 + s1;
    float mn = fminf(mn0, mn1);
    float mx = fmaxf(mx0, mx1);
#pragma unroll
    for (int o = 16; o; o >>= 1) {
        s  += __shfl_xor_sync(0xffffffffu, s, o);
        mn  = fminf(mn, __shfl_xor_sync(0xffffffffu, mn, o));
        mx  = fmaxf(mx, __shfl_xor_sync(0xffffffffu, mx, o));
    }
    if (lane == 0) {
        g_sum[plane] = s;
        g_min[plane] = mn;
        g_max[plane] = mx;
    }
}

// ---------------- kernel 2: SE MLP + per-sample min/max (proven) ------------
__global__ __launch_bounds__(256) void k2_se(const float* __restrict__ w1,
                                             const float* __restrict__ b1,
                                             const float* __restrict__ w2,
                                             const float* __restrict__ b2) {
    const int b = blockIdx.x;
    const int t = threadIdx.x;
    const int lane = t & 31, warp = t >> 5;
    __shared__ float pooled[C_];
    __shared__ float hbuf[64];

    pooled[t] = g_sum[b * C_ + t] * (1.0f / 4096.0f);
    __syncthreads();

#pragma unroll
    for (int k = 0; k < 8; ++k) {                 // 8 warps x 8 outputs, coalesced
        const int o = warp * 8 + k;
        const float* row = w1 + o * C_;
        float acc = 0.f;
#pragma unroll
        for (int j = 0; j < 8; ++j)
            acc = fmaf(row[lane + 32 * j], pooled[lane + 32 * j], acc);
#pragma unroll
        for (int sh = 16; sh; sh >>= 1)
            acc += __shfl_xor_sync(0xffffffffu, acc, sh);
        if (lane == 0) hbuf[o] = fmaxf(acc + b1[o], 0.0f);
    }
    __syncthreads();

    float v = b2[t];
    const float4* w2r = reinterpret_cast<const float4*>(w2 + t * 64);
#pragma unroll
    for (int j = 0; j < 16; ++j) {
        float4 wv = w2r[j];
        v = fmaf(hbuf[4 * j + 0], wv.x, v);
        v = fmaf(hbuf[4 * j + 1], wv.y, v);
        v = fmaf(hbuf[4 * j + 2], wv.z, v);
        v = fmaf(hbuf[4 * j + 3], wv.w, v);
    }
    float sc = fminf(fmaxf(v * (1.0f / 6.0f) + 0.5f, 0.0f), 1.0f);
    g_scale[b * C_ + t] = sc;

    float pmn = sc * g_min[b * C_ + t];           // scale >= 0
    float pmx = sc * g_max[b * C_ + t];
#pragma unroll
    for (int o = 16; o; o >>= 1) {
        pmn = fminf(pmn, __shfl_xor_sync(0xffffffffu, pmn, o));
        pmx = fmaxf(pmx, __shfl_xor_sync(0xffffffffu, pmx, o));
    }
    __shared__ float sh_mn[8], sh_mx[8];
    if (lane == 0) { sh_mn[warp] = pmn; sh_mx[warp] = pmx; }
    __syncthreads();
    if (t == 0) {
        float tmn = CUDART_INF_F, tmx = -CUDART_INF_F;
#pragma unroll
        for (int w = 0; w < 8; ++w) {
            tmn = fminf(tmn, sh_mn[w]);
            tmx = fmaxf(tmx, sh_mx[w]);
        }
        g_smin[b] = tmn;
        g_smax[b] = tmx;
    }
}

// ---------------- kernel 4: fake-quant + inline per-block (s,z) -------------
// R15's k4 (reversed planes, __stwt) + k3 folded in: each block derives its
// sample's (s, z, 1/s) from g_smin/g_smax with the SAME float ops k3 used
// (deterministic, identical across blocks). The 4 x-loads are issued FIRST
// so their DRAM latency covers the derivation.
__global__ __launch_bounds__(256) void k4_quant(const float* __restrict__ x,
                                                float* __restrict__ out,
                                                const float* __restrict__ act_range,
                                                const int*   __restrict__ cluster) {
    const int plane = (NPLANE - 1) - blockIdx.x;
    const int b = plane >> 8;
    const int t = threadIdx.x;
    const int lane = t & 31, warp = t >> 5;

    const float4* xp = reinterpret_cast<const float4*>(x   + (size_t)plane * HW_);
    float4*       op = reinterpret_cast<float4*>      (out + (size_t)plane * HW_);

    // issue all x loads up front — in flight during the (s,z) derivation
    float4 v0 = xp[t];
    float4 v1 = xp[t + 256];
    float4 v2 = xp[t + 512];
    float4 v3 = xp[t + 768];
    const float sc = g_scale[plane];

    // ---- derive (s, z, 1/s) for this sample's cluster (threads 0..63) ----
    __shared__ float sh_mn2[2], sh_mx2[2];
    __shared__ float sh_p[3];                      // ssv, zzv, inv
    const int kb = cluster[b];
    if (t < 64) {
        const int cl = cluster[t];
        float mn = (cl == kb) ? g_smin[t] : CUDART_INF_F;
        float mx = (cl == kb) ? g_smax[t] : -CUDART_INF_F;
#pragma unroll
        for (int o = 16; o; o >>= 1) {
            mn = fminf(mn, __shfl_xor_sync(0xffffffffu, mn, o));
            mx = fmaxf(mx, __shfl_xor_sync(0xffffffffu, mx, o));
        }
        if (lane == 0) { sh_mn2[warp] = mn; sh_mx2[warp] = mx; }
    }
    __syncthreads();
    if (t == 0) {
        float cmin = fminf(sh_mn2[0], sh_mn2[1]);
        float cmax = fmaxf(sh_mx2[0], sh_mx2[1]);
        const float SMOOTH = 0.995f, ONE_M = 0.005f;
        float nmin = act_range[2 * kb]     * SMOOTH + cmin * ONE_M;
        float nmax = act_range[2 * kb + 1] * SMOOTH + cmax * ONE_M;
        float s = (nmax - nmin) * (1.0f / 255.0f);  // identical ops to old k3
        sh_p[0] = s;
        sh_p[1] = -rintf(nmin / s);
        sh_p[2] = 1.0f / s;
    }
    __syncthreads();
    const float ssv = sh_p[0];
    const float zzv = sh_p[1];
    const float inv = sh_p[2];

    // ---- fake-quant ----
    float4 vv[4] = {v0, v1, v2, v3};
#pragma unroll
    for (int i = 0; i < 4; ++i) {
        float4 v = vv[i];
        float4 r;
        {
            float o = sc * v.x;
            float q = fminf(fmaxf(rintf(fmaf(o, inv, zzv)), 0.0f), 255.0f);
            r.x = (q - zzv) * ssv;
        }
        {
            float o = sc * v.y;
            float q = fminf(fmaxf(rintf(fmaf(o, inv, zzv)), 0.0f), 255.0f);
            r.y = (q - zzv) * ssv;
        }
        {
            float o = sc * v.z;
            float q = fminf(fmaxf(rintf(fmaf(o, inv, zzv)), 0.0f), 255.0f);
            r.z = (q - zzv) * ssv;
        }
        {
            float o = sc * v.w;
            float q = fminf(fmaxf(rintf(fmaf(o, inv, zzv)), 0.0f), 255.0f);
            r.w = (q - zzv) * ssv;
        }
        __stwt(&op[t + 256 * i], r);
    }
}

// ---------------- launch ----------------------------------------------------
extern "C" void kernel_launch(void* const* d_in, const int* in_sizes, int n_in,
                              void* d_out, int out_size) {
    const float* x          = (const float*)d_in[0];
    const float* w1         = (const float*)d_in[1];
    const float* b1         = (const float*)d_in[2];
    const float* w2         = (const float*)d_in[3];
    const float* b2         = (const float*)d_in[4];
    const float* act_range  = (const float*)d_in[5];
    const int*   cluster    = (const int*)d_in[6];
    float* out = (float*)d_out;

    k1_reduce<<<NPLANE / 8, 256>>>(x);
    k2_se<<<B_, 256>>>(w1, b1, w2, b2);
    k4_quant<<<NPLANE, 256>>>(x, out, act_range, cluster);
}